// round 2
// baseline (speedup 1.0000x reference)
#include <cuda_runtime.h>
#include <math.h>

// ---------------------------------------------------------------------------
// TwoDimensionalSSM: out = silu( conv4dir(x, k) + x*omega )
// Recast as 32 grouped GEMMs: Out_n (1024 x 512) = M_n (1024x1024) @ Xg_n (1024x512)
//   group n = e % 32; columns col = b*16 + e/32
// ---------------------------------------------------------------------------

#define LSIDE  32
#define SEQ    1024
#define BSZ    32
#define EMBED  512
#define NSSM   32
#define KDIM   128
#define GROUPS 32
#define GCOLS  512   // BSZ * (EMBED/NSSM) = 32*16

// Scratch (static device memory: allocation-free, graph-capturable)
__device__ float g_kpart[2][KDIM][SEQ];                       // 1 MB   (per-state-n partial impulse responses)
__device__ float g_M[(size_t)GROUPS * 1024 * 1024];           // 128 MB (combined Toeplitz operators)
__device__ float g_Xg[(size_t)GROUPS * 1024 * GCOLS];         // 64 MB  (group-major gathered x)
__device__ float g_Out[(size_t)GROUPS * 1024 * GCOLS];        // 64 MB  (GEMM result)

__device__ __forceinline__ float sigmoidf_(float v) { return 1.0f / (1.0f + expf(-v)); }

// ---------------------------------------------------------------------------
// Kernel 1: 2-D SSM recurrence -> impulse response partials per (h, state n).
// x_h[i,j] = A1*x_h[i,j-1] + A2*x_v[i,j-1] + B1*u ; x_v[i,j] = A3*x_h[i-1,j] + A4*x_v[i-1,j] + B2*u
// kpart[nn][h][i*32+j] = scale*(C1*x_h + C2*x_v)   (u = delta at (0,0))
// ---------------------------------------------------------------------------
__global__ void compute_k_kernel(const float* __restrict__ A1p, const float* __restrict__ A2p,
                                 const float* __restrict__ A3p, const float* __restrict__ A4p,
                                 const float* __restrict__ B1p, const float* __restrict__ B2p,
                                 const float* __restrict__ C1p, const float* __restrict__ C2p) {
    int g = blockIdx.x * blockDim.x + threadIdx.x;   // 0..255
    if (g >= 2 * KDIM) return;
    int h = g >> 1, nn = g & 1;
    int idx = h * 2 + nn;                            // params are (128, 2) row-major
    float A1 = sigmoidf_(A1p[idx]);
    float A2 = sigmoidf_(A2p[idx]);
    float A3 = sigmoidf_(A3p[idx]);
    float A4 = sigmoidf_(A4p[idx]);
    float B1 = sigmoidf_(B1p[idx]);
    float B2 = sigmoidf_(B2p[idx]);
    const float scale = 0.70710678118654752f;        // sqrt(1/N), N=2
    float C1 = C1p[idx] * scale;
    float C2 = C2p[idx] * scale;

    float xh_up[LSIDE], xv_up[LSIDE];
#pragma unroll
    for (int j = 0; j < LSIDE; j++) { xh_up[j] = 0.0f; xv_up[j] = 0.0f; }

    float* kout = &g_kpart[nn][h][0];
    for (int i = 0; i < LSIDE; i++) {
        float xh_prev = 0.0f;
        float xv_prev = 0.0f;
        for (int j = 0; j < LSIDE; j++) {
            float u = (i == 0 && j == 0) ? 1.0f : 0.0f;
            float xv_new  = A3 * xh_up[j] + A4 * xv_up[j] + B2 * u;
            float xv_left = (j == 0) ? 0.0f : xv_prev;
            float xh_new  = A1 * xh_prev + A2 * xv_left + B1 * u;
            kout[i * LSIDE + j] = C1 * xh_new + C2 * xv_new;
            xh_up[j] = xh_new;
            xv_up[j] = xv_new;
            xh_prev = xh_new;
            xv_prev = xv_new;
        }
    }
}

// ---------------------------------------------------------------------------
// Kernel 2: build M_n[(i,j),(u,v)] from the 4 directional kernels of group n.
//  dir0: u<=i, v<=j : k[0*32+n][i-u][j-v]      dir1: u>=i, v<=j : k[1*32+n][u-i][j-v]
//  dir2: u<=i, v>=j : k[2*32+n][i-u][v-j]      dir3: u>=i, v>=j : k[3*32+n][u-i][v-j]
//  Boundary factors (x2 on row 0 / col 0, net x1 at (0,0)) baked into smem copy.
// ---------------------------------------------------------------------------
__global__ void build_M_kernel() {
    int n  = blockIdx.y;         // group
    int sp = blockIdx.x;         // output pixel (i,j), 0..1023
    __shared__ float sk[4 * 1024];
    int tid = threadIdx.x;       // 256 threads
#pragma unroll
    for (int it = 0; it < 16; it++) {
        int idx = tid + it * 256;           // 0..4095
        int d  = idx >> 10;
        int ab = idx & 1023;
        int a = ab >> 5, b = ab & 31;
        float v = g_kpart[0][d * NSSM + n][ab] + g_kpart[1][d * NSSM + n][ab];
        float f = 1.0f;
        if (!(a == 0 && b == 0)) {
            if (a == 0) f *= 2.0f;
            if (b == 0) f *= 2.0f;
        }
        sk[idx] = v * f;
    }
    __syncthreads();

    int i = sp >> 5, j = sp & 31;
    int s0 = tid * 4;
    float vals[4];
#pragma unroll
    for (int c = 0; c < 4; c++) {
        int s = s0 + c;
        int u = s >> 5, v = s & 31;
        float val = 0.0f;
        if (u <= i && v <= j) val += sk[0 * 1024 + (i - u) * 32 + (j - v)];
        if (u >= i && v <= j) val += sk[1 * 1024 + (u - i) * 32 + (j - v)];
        if (u <= i && v >= j) val += sk[2 * 1024 + (i - u) * 32 + (v - j)];
        if (u >= i && v >= j) val += sk[3 * 1024 + (u - i) * 32 + (v - j)];
        vals[c] = val;
    }
    float4* dst = (float4*)&g_M[((size_t)n << 20) + (size_t)sp * 1024 + s0];
    *dst = make_float4(vals[0], vals[1], vals[2], vals[3]);
}

// ---------------------------------------------------------------------------
// Kernel 3: gather x (S,B,E) -> Xg[n][s][b*16 + e/32]  (coalesced via smem)
// ---------------------------------------------------------------------------
__global__ void transpose_kernel(const float* __restrict__ x) {
    int blk = blockIdx.x;                 // 0..32767
    int s = blk & 1023, b = blk >> 10;
    __shared__ float sm[16 * 33 + 33];
    int tid = threadIdx.x;                // 512 threads; phase1: tid == e
    float v = x[(size_t)s * (BSZ * EMBED) + (size_t)b * EMBED + tid];
    sm[(tid >> 5) * 33 + (tid & 31)] = v; // [r][n] with pad
    __syncthreads();
    int nn = tid >> 4, r = tid & 15;      // phase2
    g_Xg[((size_t)nn * 1024 * GCOLS) + (size_t)s * GCOLS + b * 16 + r] = sm[r * 33 + nn];
}

// ---------------------------------------------------------------------------
// Kernel 4: grouped GEMM  Out_n = M_n (1024x1024) @ Xg_n (1024x512)
// 128x128 tile, BK=8, 256 threads, 8x8 per thread, register prefetch.
// ---------------------------------------------------------------------------
__global__ __launch_bounds__(256) void gemm_kernel() {
    int n  = blockIdx.z;
    int m0 = blockIdx.y << 7;       // sp tile
    int n0 = blockIdx.x << 7;       // col tile
    const float* A = g_M   + ((size_t)n << 20);
    const float* B = g_Xg  + ((size_t)n * 1024 * GCOLS);
    float*       C = g_Out + ((size_t)n * 1024 * GCOLS);

    __shared__ float As[8][128];
    __shared__ float Bs[8][128];

    int tid = threadIdx.x;
    int tx = tid & 15, ty = tid >> 4;
    int aRow = tid >> 1,  aCol = (tid & 1) << 2;
    int bRow = tid >> 5,  bCol = (tid & 31) << 2;

    const float* aPtr = A + (size_t)(m0 + aRow) * 1024 + aCol;
    const float* bPtr = B + (size_t)bRow * GCOLS + n0 + bCol;

    float acc[8][8];
#pragma unroll
    for (int i2 = 0; i2 < 8; i2++)
#pragma unroll
        for (int j2 = 0; j2 < 8; j2++) acc[i2][j2] = 0.0f;

    float4 av = *(const float4*)aPtr;
    float4 bv = *(const float4*)bPtr;

    for (int k0 = 0; k0 < 1024; k0 += 8) {
        As[aCol + 0][aRow] = av.x;
        As[aCol + 1][aRow] = av.y;
        As[aCol + 2][aRow] = av.z;
        As[aCol + 3][aRow] = av.w;
        *(float4*)&Bs[bRow][bCol] = bv;
        __syncthreads();

        if (k0 + 8 < 1024) {
            av = *(const float4*)(aPtr + (k0 + 8));
            bv = *(const float4*)(bPtr + (size_t)(k0 + 8) * GCOLS);
        }

#pragma unroll
        for (int kk = 0; kk < 8; kk++) {
            float a[8], b[8];
            *(float4*)(a)     = *(const float4*)&As[kk][ty * 8];
            *(float4*)(a + 4) = *(const float4*)&As[kk][ty * 8 + 4];
            *(float4*)(b)     = *(const float4*)&Bs[kk][tx * 8];
            *(float4*)(b + 4) = *(const float4*)&Bs[kk][tx * 8 + 4];
#pragma unroll
            for (int i2 = 0; i2 < 8; i2++)
#pragma unroll
                for (int j2 = 0; j2 < 8; j2++)
                    acc[i2][j2] = fmaf(a[i2], b[j2], acc[i2][j2]);
        }
        __syncthreads();
    }

#pragma unroll
    for (int i2 = 0; i2 < 8; i2++) {
        float* crow = C + (size_t)(m0 + ty * 8 + i2) * GCOLS + n0 + tx * 8;
        *(float4*)(crow)     = make_float4(acc[i2][0], acc[i2][1], acc[i2][2], acc[i2][3]);
        *(float4*)(crow + 4) = make_float4(acc[i2][4], acc[i2][5], acc[i2][6], acc[i2][7]);
    }
}

// ---------------------------------------------------------------------------
// Kernel 5: un-gather Out + residual x*omega + SiLU -> d_out (S,B,E) fp32
// ---------------------------------------------------------------------------
__global__ void epilogue_kernel(const float* __restrict__ x, const float* __restrict__ omega,
                                float* __restrict__ out) {
    int blk = blockIdx.x;
    int s = blk & 1023, b = blk >> 10;
    __shared__ float sm[16 * 33 + 33];
    int tid = threadIdx.x;                // 512
    int nn = tid >> 4, r = tid & 15;      // phase1: coalesced read of Out
    sm[r * 33 + nn] = g_Out[((size_t)nn * 1024 * GCOLS) + (size_t)s * GCOLS + b * 16 + r];
    __syncthreads();
    size_t off = (size_t)s * (BSZ * EMBED) + (size_t)b * EMBED + tid;   // phase2: tid == e
    float conv = sm[(tid >> 5) * 33 + (tid & 31)];
    float z = conv + x[off] * omega[tid];
    out[off] = z / (1.0f + expf(-z));     // silu
}

// ---------------------------------------------------------------------------
extern "C" void kernel_launch(void* const* d_in, const int* in_sizes, int n_in,
                              void* d_out, int out_size) {
    const float* x     = (const float*)d_in[0];
    const float* A1    = (const float*)d_in[1];
    const float* A2    = (const float*)d_in[2];
    const float* A3    = (const float*)d_in[3];
    const float* A4    = (const float*)d_in[4];
    const float* B1    = (const float*)d_in[5];
    const float* B2    = (const float*)d_in[6];
    const float* C1    = (const float*)d_in[7];
    const float* C2    = (const float*)d_in[8];
    const float* omega = (const float*)d_in[9];
    float* out = (float*)d_out;

    compute_k_kernel<<<8, 32>>>(A1, A2, A3, A4, B1, B2, C1, C2);
    build_M_kernel<<<dim3(1024, GROUPS), 256>>>();
    transpose_kernel<<<SEQ * BSZ, 512>>>(x);
    gemm_kernel<<<dim3(GCOLS / 128, 1024 / 128, GROUPS), 256>>>();
    epilogue_kernel<<<SEQ * BSZ, 512>>>(x, omega, out);
}

// round 5
// speedup vs baseline: 2.9441x; 2.9441x over previous
#include <cuda_runtime.h>
#include <cuda_fp16.h>
#include <math.h>
#include <stdint.h>

// ---------------------------------------------------------------------------
// TwoDimensionalSSM: out = silu( conv4dir(x, k) + x*omega )
// 32 grouped GEMMs via mma.sync (HMMA, fp16 in / fp32 accum):
//   Out_n (1024 x 512) = M_n (1024x1024) @ X_n^T,  group n = e % 32
//   column c = b*16 + (e/32)
// ---------------------------------------------------------------------------

#define LSIDE  32
#define SEQ    1024
#define BSZ    32
#define EMBED  512
#define NSSM   32
#define KDIM   128
#define GROUPS 32
#define GCOLS  512

// Static device scratch (allocation-free, graph-capturable)
__device__ float  g_kpart[2][KDIM][SEQ];                             // 1 MB
__device__ __align__(16) __half g_M[(size_t)GROUPS * 1024 * 1024];   // 64 MB  [n][sp][s]
__device__ __align__(16) __half g_X[(size_t)GROUPS * GCOLS * 1024];  // 32 MB  [n][c][s]
__device__ __align__(16) float  g_Out[(size_t)GROUPS * 1024 * GCOLS];// 64 MB  [n][sp][c]

__device__ __forceinline__ float sigmoidf_(float v) { return 1.0f / (1.0f + expf(-v)); }

__device__ __forceinline__ uint32_t smem_u32(const void* p) {
    return (uint32_t)__cvta_generic_to_shared(p);
}
__device__ __forceinline__ void cp_async16(uint32_t dst, const void* src) {
    asm volatile("cp.async.cg.shared.global [%0], [%1], 16;" :: "r"(dst), "l"(src) : "memory");
}
__device__ __forceinline__ void cp_commit() {
    asm volatile("cp.async.commit_group;" ::: "memory");
}
__device__ __forceinline__ void ldsm_x4(uint32_t* r, uint32_t addr) {
    asm volatile("ldmatrix.sync.aligned.m8n8.x4.shared.b16 {%0,%1,%2,%3}, [%4];"
                 : "=r"(r[0]), "=r"(r[1]), "=r"(r[2]), "=r"(r[3]) : "r"(addr));
}
__device__ __forceinline__ void mma16816(float* c, const uint32_t* a, uint32_t b0, uint32_t b1) {
    asm volatile(
        "mma.sync.aligned.m16n8k16.row.col.f32.f16.f16.f32 "
        "{%0,%1,%2,%3}, {%4,%5,%6,%7}, {%8,%9}, {%0,%1,%2,%3};"
        : "+f"(c[0]), "+f"(c[1]), "+f"(c[2]), "+f"(c[3])
        : "r"(a[0]), "r"(a[1]), "r"(a[2]), "r"(a[3]), "r"(b0), "r"(b1));
}

// ---------------------------------------------------------------------------
// Kernel 1: 2-D SSM recurrence -> impulse response partials per (h, state n).
// ---------------------------------------------------------------------------
__global__ void compute_k_kernel(const float* __restrict__ A1p, const float* __restrict__ A2p,
                                 const float* __restrict__ A3p, const float* __restrict__ A4p,
                                 const float* __restrict__ B1p, const float* __restrict__ B2p,
                                 const float* __restrict__ C1p, const float* __restrict__ C2p) {
    int g = blockIdx.x * blockDim.x + threadIdx.x;
    if (g >= 2 * KDIM) return;
    int h = g >> 1, nn = g & 1;
    int idx = h * 2 + nn;
    float A1 = sigmoidf_(A1p[idx]);
    float A2 = sigmoidf_(A2p[idx]);
    float A3 = sigmoidf_(A3p[idx]);
    float A4 = sigmoidf_(A4p[idx]);
    float B1 = sigmoidf_(B1p[idx]);
    float B2 = sigmoidf_(B2p[idx]);
    const float scale = 0.70710678118654752f;
    float C1 = C1p[idx] * scale;
    float C2 = C2p[idx] * scale;

    float xh_up[LSIDE], xv_up[LSIDE];
#pragma unroll
    for (int j = 0; j < LSIDE; j++) { xh_up[j] = 0.0f; xv_up[j] = 0.0f; }

    float* kout = &g_kpart[nn][h][0];
    for (int i = 0; i < LSIDE; i++) {
        float xh_prev = 0.0f, xv_prev = 0.0f;
        for (int j = 0; j < LSIDE; j++) {
            float u = (i == 0 && j == 0) ? 1.0f : 0.0f;
            float xv_new  = A3 * xh_up[j] + A4 * xv_up[j] + B2 * u;
            float xv_left = (j == 0) ? 0.0f : xv_prev;
            float xh_new  = A1 * xh_prev + A2 * xv_left + B1 * u;
            kout[i * LSIDE + j] = C1 * xh_new + C2 * xv_new;
            xh_up[j] = xh_new; xv_up[j] = xv_new;
            xh_prev  = xh_new; xv_prev  = xv_new;
        }
    }
}

// ---------------------------------------------------------------------------
// Kernel 2: build M_n rows from the 4 directional kernels, store fp16.
// ---------------------------------------------------------------------------
__global__ void build_M_kernel() {
    int n  = blockIdx.y;
    int sp = blockIdx.x;
    __shared__ float sk[4 * 1024];
    int tid = threadIdx.x;   // 256
#pragma unroll
    for (int it = 0; it < 16; it++) {
        int idx = tid + it * 256;
        int d  = idx >> 10;
        int ab = idx & 1023;
        int a = ab >> 5, b = ab & 31;
        float v = g_kpart[0][d * NSSM + n][ab] + g_kpart[1][d * NSSM + n][ab];
        float f = 1.0f;
        if (!(a == 0 && b == 0)) {
            if (a == 0) f *= 2.0f;
            if (b == 0) f *= 2.0f;
        }
        sk[idx] = v * f;
    }
    __syncthreads();

    int i = sp >> 5, j = sp & 31;
    int s0 = tid * 4;
    float vals[4];
#pragma unroll
    for (int c = 0; c < 4; c++) {
        int s = s0 + c;
        int u = s >> 5, v = s & 31;
        float val = 0.0f;
        if (u <= i && v <= j) val += sk[0 * 1024 + (i - u) * 32 + (j - v)];
        if (u >= i && v <= j) val += sk[1 * 1024 + (u - i) * 32 + (j - v)];
        if (u <= i && v >= j) val += sk[2 * 1024 + (i - u) * 32 + (v - j)];
        if (u >= i && v >= j) val += sk[3 * 1024 + (u - i) * 32 + (v - j)];
        vals[c] = val;
    }
    size_t off = ((size_t)n << 20) + (size_t)sp * 1024 + s0;
    *(__half2*)&g_M[off]     = __floats2half2_rn(vals[0], vals[1]);
    *(__half2*)&g_M[off + 2] = __floats2half2_rn(vals[2], vals[3]);
}

// ---------------------------------------------------------------------------
// Kernel 3: gather/transpose x (S,B,E) fp32 -> g_X[n][c][s] fp16  (c=b*16+e/32)
// ---------------------------------------------------------------------------
__global__ __launch_bounds__(256) void transpose_kernel(const float* __restrict__ x) {
    __shared__ __half sm[32][520];
    int b  = blockIdx.x & 31;
    int s0 = (blockIdx.x >> 5) << 5;
    int t = threadIdx.x;
#pragma unroll
    for (int i = 0; i < 64; ++i) {
        int idx = t + (i << 8);
        int si = idx >> 9, e = idx & 511;
        sm[si][e] = __float2half_rn(x[(size_t)(s0 + si) * (BSZ * EMBED) + (size_t)b * EMBED + e]);
    }
    __syncthreads();
#pragma unroll
    for (int i = 0; i < 8; ++i) {
        int c2 = t + (i << 8);
        int pair = c2 >> 2, sj = (c2 & 3) << 3;
        int nn = pair & 31, r = pair >> 5;
        int e = (r << 5) + nn;
        __half tmp[8];
#pragma unroll
        for (int q = 0; q < 8; ++q) tmp[q] = sm[sj + q][e];
        *(uint4*)&g_X[((size_t)nn * GCOLS + b * 16 + r) * 1024 + s0 + sj] = *(uint4*)tmp;
    }
}

// ---------------------------------------------------------------------------
// Kernel 4: HMMA grouped GEMM.  CTA: 128(M)x64(N) tile, K in 16 chunks of 64,
// double-buffered cp.async, 8 warps (4M x 2N), warp tile 32x32.
// Smem: A 2 stages x 16KB + B 2 stages x 8KB = 48KB (static cap).
// Row layout: [row][k0..63] halfs, 128B/row, SW128 XOR swizzle:
//   byte = row*128 + (kbyte ^ ((row&7)<<4))
// ---------------------------------------------------------------------------
__global__ __launch_bounds__(256) void gemm_kernel() {
    __shared__ __align__(1024) __half sbuf[(2 * 128 + 2 * 64) * 64];   // 48 KB
    const int n  = blockIdx.z;
    const int m0 = blockIdx.y << 7;
    const int n0 = blockIdx.x << 6;
    const __half* Ag = g_M + ((size_t)n << 20);
    const __half* Bg = g_X + ((size_t)n << 19);

    const int tid = threadIdx.x;
    const int wid = tid >> 5;
    const int lane = tid & 31;
    const int wm = wid & 3;          // 4 warps along M (32 rows each)
    const int wn = wid >> 2;         // 2 warps along N (32 cols each)

    const uint32_t sbase = smem_u32(sbuf);
    const uint32_t A_SZ = 128 * 64 * 2;   // 16 KB per A stage
    const uint32_t B_SZ = 64 * 64 * 2;    // 8 KB per B stage
    const uint32_t B_OFF = 2 * A_SZ;      // B region starts at 32 KB

    auto load_chunk = [&](int c, int st) {
        int k0 = c << 6;
#pragma unroll
        for (int i = 0; i < 4; ++i) {            // A: 128 rows x 8 x 16B
            int id  = tid + (i << 8);            // 0..1023
            int row = id >> 3, k8 = id & 7;
            uint32_t sw = (uint32_t)(row * 128 + ((k8 << 4) ^ ((row & 7) << 4)));
            cp_async16(sbase + st * A_SZ + sw,
                       Ag + (size_t)(m0 + row) * 1024 + k0 + (k8 << 3));
        }
#pragma unroll
        for (int i = 0; i < 2; ++i) {            // B: 64 rows x 8 x 16B
            int id  = tid + (i << 8);            // 0..511
            int row = id >> 3, k8 = id & 7;
            uint32_t sw = (uint32_t)(row * 128 + ((k8 << 4) ^ ((row & 7) << 4)));
            cp_async16(sbase + B_OFF + st * B_SZ + sw,
                       Bg + (size_t)(n0 + row) * 1024 + k0 + (k8 << 3));
        }
        cp_commit();
    };

    load_chunk(0, 0);
    load_chunk(1, 1);

    float acc[2][4][4];
#pragma unroll
    for (int mi = 0; mi < 2; mi++)
#pragma unroll
        for (int nj = 0; nj < 4; nj++)
#pragma unroll
            for (int q = 0; q < 4; q++) acc[mi][nj][q] = 0.0f;

    // ldmatrix lane geometry
    // A x4 tiles: lanes 0-7 (mlo,klo), 8-15 (mhi,klo), 16-23 (mlo,khi), 24-31 (mhi,khi)
    int aRow0 = wm * 32 + (lane & 7) + (lane & 8);          // + mi*16
    uint32_t aKsel = (uint32_t)(lane & 16);                 // 0 or 16 bytes
    // B x4 tiles: lanes 0-7 (nlo,klo), 8-15 (nlo,khi), 16-23 (nhi,klo), 24-31 (nhi,khi)
    int bRow0 = wn * 32 + (lane & 7) + ((lane & 16) >> 1);  // + p*16
    uint32_t bKsel = (uint32_t)((lane & 8) << 1);           // 0 or 16 bytes

    for (int c = 0; c < 16; ++c) {
        if (c < 15) asm volatile("cp.async.wait_group 1;" ::: "memory");
        else        asm volatile("cp.async.wait_group 0;" ::: "memory");
        __syncthreads();

        uint32_t aS = sbase + (uint32_t)(c & 1) * A_SZ;
        uint32_t bS = sbase + B_OFF + (uint32_t)(c & 1) * B_SZ;

#pragma unroll
        for (int ks = 0; ks < 4; ++ks) {
            uint32_t a[2][4];
#pragma unroll
            for (int mi = 0; mi < 2; mi++) {
                int row = aRow0 + mi * 16;
                uint32_t addr = aS + (uint32_t)(row * 128)
                              + (((uint32_t)(ks * 32) + aKsel) ^ (uint32_t)((row & 7) << 4));
                ldsm_x4(a[mi], addr);
            }
            uint32_t b[2][4];
#pragma unroll
            for (int p = 0; p < 2; p++) {
                int row = bRow0 + p * 16;
                uint32_t addr = bS + (uint32_t)(row * 128)
                              + (((uint32_t)(ks * 32) + bKsel) ^ (uint32_t)((row & 7) << 4));
                ldsm_x4(b[p], addr);
            }
#pragma unroll
            for (int mi = 0; mi < 2; mi++)
#pragma unroll
                for (int nj = 0; nj < 4; nj++) {
                    int p = nj >> 1, e = (nj & 1) << 1;
                    mma16816(acc[mi][nj], a[mi], b[p][e], b[p][e + 1]);
                }
        }
        __syncthreads();
        if (c + 2 < 16) load_chunk(c + 2, c & 1);
    }

    // writeout fp32 accumulators
    float* C = g_Out + ((size_t)n << 19);
    int colBase = n0 + wn * 32 + ((lane & 3) << 1);
    int rowBase = m0 + wm * 32 + (lane >> 2);
#pragma unroll
    for (int mi = 0; mi < 2; mi++) {
        int r = rowBase + mi * 16;
#pragma unroll
        for (int nj = 0; nj < 4; nj++) {
            int col = colBase + nj * 8;
            *(float2*)&C[(size_t)r * GCOLS + col]       = make_float2(acc[mi][nj][0], acc[mi][nj][1]);
            *(float2*)&C[(size_t)(r + 8) * GCOLS + col] = make_float2(acc[mi][nj][2], acc[mi][nj][3]);
        }
    }
}

// ---------------------------------------------------------------------------
// Kernel 5: un-gather Out + residual x*omega + SiLU -> d_out (S,B,E) fp32
// ---------------------------------------------------------------------------
__global__ void epilogue_kernel(const float* __restrict__ x, const float* __restrict__ omega,
                                float* __restrict__ out) {
    int blk = blockIdx.x;
    int s = blk & 1023, b = blk >> 10;
    __shared__ float sm[16 * 33 + 33];
    int tid = threadIdx.x;                // 512
    int nn = tid >> 4, r = tid & 15;
    sm[r * 33 + nn] = g_Out[((size_t)nn << 19) + (size_t)s * GCOLS + b * 16 + r];
    __syncthreads();
    size_t off = (size_t)s * (BSZ * EMBED) + (size_t)b * EMBED + tid;
    float conv = sm[(tid >> 5) * 33 + (tid & 31)];
    float z = conv + x[off] * omega[tid];
    out[off] = z / (1.0f + expf(-z));
}

// ---------------------------------------------------------------------------
extern "C" void kernel_launch(void* const* d_in, const int* in_sizes, int n_in,
                              void* d_out, int out_size) {
    const float* x     = (const float*)d_in[0];
    const float* A1    = (const float*)d_in[1];
    const float* A2    = (const float*)d_in[2];
    const float* A3    = (const float*)d_in[3];
    const float* A4    = (const float*)d_in[4];
    const float* B1    = (const float*)d_in[5];
    const float* B2    = (const float*)d_in[6];
    const float* C1    = (const float*)d_in[7];
    const float* C2    = (const float*)d_in[8];
    const float* omega = (const float*)d_in[9];
    float* out = (float*)d_out;

    compute_k_kernel<<<8, 32>>>(A1, A2, A3, A4, B1, B2, C1, C2);
    build_M_kernel<<<dim3(1024, GROUPS), 256>>>();
    transpose_kernel<<<SEQ * BSZ / 32, 256>>>(x);
    gemm_kernel<<<dim3(GCOLS / 64, 1024 / 128, GROUPS), 256>>>();
    epilogue_kernel<<<SEQ * BSZ, 512>>>(x, omega, out);
}

// round 6
// speedup vs baseline: 3.8744x; 1.3160x over previous
#include <cuda_runtime.h>
#include <cuda_fp16.h>
#include <math.h>
#include <stdint.h>

// ---------------------------------------------------------------------------
// TwoDimensionalSSM: out = silu( conv4dir(x, k) + x*omega )
// 32 grouped GEMMs via mma.sync (HMMA, fp16 in / fp32 accum):
//   Out_n (1024 x 512) = M_n (1024x1024) @ X_n^T,  group n = e % 32
//   column c = b*16 + (e/32)
// ---------------------------------------------------------------------------

#define LSIDE  32
#define SEQ    1024
#define BSZ    32
#define EMBED  512
#define NSSM   32
#define KDIM   128
#define GROUPS 32
#define GCOLS  512

// Static device scratch (allocation-free, graph-capturable)
__device__ float  g_kpart[2][KDIM][SEQ];                             // 1 MB
__device__ __align__(16) __half g_M[(size_t)GROUPS * 1024 * 1024];   // 64 MB  [n][sp][s]
__device__ __align__(16) __half g_X[(size_t)GROUPS * GCOLS * 1024];  // 32 MB  [n][c][s]
__device__ __align__(16) float  g_Out[(size_t)GROUPS * 1024 * GCOLS];// 64 MB  [n][sp][c]

__device__ __forceinline__ float sigmoidf_(float v) { return 1.0f / (1.0f + expf(-v)); }

__device__ __forceinline__ uint32_t smem_u32(const void* p) {
    return (uint32_t)__cvta_generic_to_shared(p);
}
__device__ __forceinline__ void cp_async16(uint32_t dst, const void* src) {
    asm volatile("cp.async.cg.shared.global [%0], [%1], 16;" :: "r"(dst), "l"(src) : "memory");
}
__device__ __forceinline__ void cp_commit() {
    asm volatile("cp.async.commit_group;" ::: "memory");
}
__device__ __forceinline__ void ldsm_x4(uint32_t* r, uint32_t addr) {
    asm volatile("ldmatrix.sync.aligned.m8n8.x4.shared.b16 {%0,%1,%2,%3}, [%4];"
                 : "=r"(r[0]), "=r"(r[1]), "=r"(r[2]), "=r"(r[3]) : "r"(addr));
}
__device__ __forceinline__ void mma16816(float* c, const uint32_t* a, uint32_t b0, uint32_t b1) {
    asm volatile(
        "mma.sync.aligned.m16n8k16.row.col.f32.f16.f16.f32 "
        "{%0,%1,%2,%3}, {%4,%5,%6,%7}, {%8,%9}, {%0,%1,%2,%3};"
        : "+f"(c[0]), "+f"(c[1]), "+f"(c[2]), "+f"(c[3])
        : "r"(a[0]), "r"(a[1]), "r"(a[2]), "r"(a[3]), "r"(b0), "r"(b1));
}

// ---------------------------------------------------------------------------
// Kernel 1: 2-D SSM recurrence -> impulse response partials per (h, state n).
// ---------------------------------------------------------------------------
__global__ void compute_k_kernel(const float* __restrict__ A1p, const float* __restrict__ A2p,
                                 const float* __restrict__ A3p, const float* __restrict__ A4p,
                                 const float* __restrict__ B1p, const float* __restrict__ B2p,
                                 const float* __restrict__ C1p, const float* __restrict__ C2p) {
    int g = blockIdx.x * blockDim.x + threadIdx.x;
    if (g >= 2 * KDIM) return;
    int h = g >> 1, nn = g & 1;
    int idx = h * 2 + nn;
    float A1 = sigmoidf_(A1p[idx]);
    float A2 = sigmoidf_(A2p[idx]);
    float A3 = sigmoidf_(A3p[idx]);
    float A4 = sigmoidf_(A4p[idx]);
    float B1 = sigmoidf_(B1p[idx]);
    float B2 = sigmoidf_(B2p[idx]);
    const float scale = 0.70710678118654752f;
    float C1 = C1p[idx] * scale;
    float C2 = C2p[idx] * scale;

    float xh_up[LSIDE], xv_up[LSIDE];
#pragma unroll
    for (int j = 0; j < LSIDE; j++) { xh_up[j] = 0.0f; xv_up[j] = 0.0f; }

    float* kout = &g_kpart[nn][h][0];
    for (int i = 0; i < LSIDE; i++) {
        float xh_prev = 0.0f, xv_prev = 0.0f;
        for (int j = 0; j < LSIDE; j++) {
            float u = (i == 0 && j == 0) ? 1.0f : 0.0f;
            float xv_new  = A3 * xh_up[j] + A4 * xv_up[j] + B2 * u;
            float xv_left = (j == 0) ? 0.0f : xv_prev;
            float xh_new  = A1 * xh_prev + A2 * xv_left + B1 * u;
            kout[i * LSIDE + j] = C1 * xh_new + C2 * xv_new;
            xh_up[j] = xh_new; xv_up[j] = xv_new;
            xh_prev  = xh_new; xv_prev  = xv_new;
        }
    }
}

// ---------------------------------------------------------------------------
// Kernel 2: build M_n, 32 sp-rows per block (amortize the sk table load 32x).
// grid = (32 i-slabs, 32 groups), 256 threads.
// ---------------------------------------------------------------------------
__global__ __launch_bounds__(256) void build_M_kernel() {
    int i = blockIdx.x;          // sp row-slab: rows sp = i*32 + j
    int n = blockIdx.y;          // group
    __shared__ float sk[4 * 1024];
    int tid = threadIdx.x;
#pragma unroll
    for (int it = 0; it < 16; it++) {
        int idx = tid + it * 256;
        int d  = idx >> 10;
        int ab = idx & 1023;
        int a = ab >> 5, b = ab & 31;
        float v = g_kpart[0][d * NSSM + n][ab] + g_kpart[1][d * NSSM + n][ab];
        float f = 1.0f;
        if (!(a == 0 && b == 0)) {
            if (a == 0) f *= 2.0f;
            if (b == 0) f *= 2.0f;
        }
        sk[idx] = v * f;
    }
    __syncthreads();

    int s0 = tid * 4;
    const int u0 = s0 >> 5, v0 = s0 & 31;   // 4 consecutive s share u; v0..v0+3
    for (int j2 = 0; j2 < 32; j2++) {
        int sp = i * 32 + j2;
        int j = sp & 31;
        float vals[4];
#pragma unroll
        for (int c = 0; c < 4; c++) {
            int u = u0, v = v0 + c;
            float val = 0.0f;
            if (u <= i && v <= j) val += sk[0 * 1024 + (i - u) * 32 + (j - v)];
            if (u >= i && v <= j) val += sk[1 * 1024 + (u - i) * 32 + (j - v)];
            if (u <= i && v >= j) val += sk[2 * 1024 + (i - u) * 32 + (v - j)];
            if (u >= i && v >= j) val += sk[3 * 1024 + (u - i) * 32 + (v - j)];
            vals[c] = val;
        }
        size_t off = ((size_t)n << 20) + (size_t)sp * 1024 + s0;
        *(__half2*)&g_M[off]     = __floats2half2_rn(vals[0], vals[1]);
        *(__half2*)&g_M[off + 2] = __floats2half2_rn(vals[2], vals[3]);
    }
}

// ---------------------------------------------------------------------------
// Kernel 3: gather/transpose x (S,B,E) fp32 -> g_X[n][c][s] fp16  (c=b*16+e/32)
// ---------------------------------------------------------------------------
__global__ __launch_bounds__(256) void transpose_kernel(const float* __restrict__ x) {
    __shared__ __half sm[32][520];
    int b  = blockIdx.x & 31;
    int s0 = (blockIdx.x >> 5) << 5;
    int t = threadIdx.x;
#pragma unroll
    for (int i = 0; i < 64; ++i) {
        int idx = t + (i << 8);
        int si = idx >> 9, e = idx & 511;
        sm[si][e] = __float2half_rn(x[(size_t)(s0 + si) * (BSZ * EMBED) + (size_t)b * EMBED + e]);
    }
    __syncthreads();
#pragma unroll
    for (int i = 0; i < 8; ++i) {
        int c2 = t + (i << 8);
        int pair = c2 >> 2, sj = (c2 & 3) << 3;
        int nn = pair & 31, r = pair >> 5;
        int e = (r << 5) + nn;
        __half tmp[8];
#pragma unroll
        for (int q = 0; q < 8; ++q) tmp[q] = sm[sj + q][e];
        *(uint4*)&g_X[((size_t)nn * GCOLS + b * 16 + r) * 1024 + s0 + sj] = *(uint4*)tmp;
    }
}

// ---------------------------------------------------------------------------
// Kernel 4: HMMA grouped GEMM. CTA tile 128(M)x128(N), BK=32, 3-stage
// cp.async pipeline (3 x (8KB A + 8KB B) = 48 KB). 8 warps (4M x 2N),
// warp tile 32x64. Smem rows are 64B; swizzle:
//   byte = row*64 + (kbyte ^ (((row>>1)&3)<<4))
// keeps ldmatrix 8-row phases conflict-free (row parity alternates 64B halves).
// ---------------------------------------------------------------------------
__global__ __launch_bounds__(256) void gemm_kernel() {
    __shared__ __align__(1024) __half sbuf[3 * 256 * 32];   // 48 KB
    const int n  = blockIdx.z;
    const int m0 = blockIdx.y << 7;
    const int n0 = blockIdx.x << 7;
    const __half* Ag = g_M + ((size_t)n << 20);
    const __half* Bg = g_X + ((size_t)n << 19);

    const int tid = threadIdx.x;
    const int wid = tid >> 5;
    const int lane = tid & 31;
    const int wm = wid & 3;          // 4 warps along M (32 rows each)
    const int wn = wid >> 2;         // 2 warps along N (64 cols each)

    const uint32_t sbase = smem_u32(sbuf);
    const uint32_t STG = 16384;      // bytes per stage (A 8KB + B 8KB)

    auto load_chunk = [&](int c, int st) {
        int k0 = c << 5;             // halfs
#pragma unroll
        for (int i = 0; i < 2; ++i) {
            int id  = tid + (i << 8);          // 0..511
            int row = id >> 2, ch = id & 3;
            uint32_t sw = (uint32_t)(row * 64 + ((ch << 4) ^ (((row >> 1) & 3) << 4)));
            cp_async16(sbase + (uint32_t)st * STG + sw,
                       Ag + (size_t)(m0 + row) * 1024 + k0 + (ch << 3));
            cp_async16(sbase + (uint32_t)st * STG + 8192 + sw,
                       Bg + (size_t)(n0 + row) * 1024 + k0 + (ch << 3));
        }
        cp_commit();
    };

    load_chunk(0, 0);
    load_chunk(1, 1);
    load_chunk(2, 2);

    float acc[2][8][4];
#pragma unroll
    for (int mi = 0; mi < 2; mi++)
#pragma unroll
        for (int nj = 0; nj < 8; nj++)
#pragma unroll
            for (int q = 0; q < 4; q++) acc[mi][nj][q] = 0.0f;

    // ldmatrix lane geometry
    // A x4 tiles: lanes 0-7 (mlo,klo), 8-15 (mhi,klo), 16-23 (mlo,khi), 24-31 (mhi,khi)
    const int aRow0 = wm * 32 + (lane & 15);                // + mi*16
    const uint32_t aKsel = (uint32_t)(lane & 16);           // 0 or 16 bytes
    // B x4 tiles: lanes 0-7 (nlo,klo), 8-15 (nlo,khi), 16-23 (nhi,klo), 24-31 (nhi,khi)
    const int bRow0 = wn * 64 + (lane & 7) + ((lane & 16) >> 1);   // + p*16
    const uint32_t bKsel = (uint32_t)((lane & 8) << 1);     // 0 or 16 bytes

    int st = 0;
    for (int c = 0; c < 32; ++c) {
        if (c < 30)       asm volatile("cp.async.wait_group 2;" ::: "memory");
        else if (c == 30) asm volatile("cp.async.wait_group 1;" ::: "memory");
        else              asm volatile("cp.async.wait_group 0;" ::: "memory");
        __syncthreads();

        uint32_t aS = sbase + (uint32_t)st * STG;
        uint32_t bS = aS + 8192;

#pragma unroll
        for (int ks = 0; ks < 2; ++ks) {
            uint32_t a[2][4];
#pragma unroll
            for (int mi = 0; mi < 2; mi++) {
                int row = aRow0 + mi * 16;
                uint32_t kb = (uint32_t)(ks << 5) + aKsel;
                uint32_t addr = aS + (uint32_t)(row * 64)
                              + (kb ^ (uint32_t)(((row >> 1) & 3) << 4));
                ldsm_x4(a[mi], addr);
            }
            uint32_t b[4][4];
#pragma unroll
            for (int p = 0; p < 4; p++) {
                int row = bRow0 + p * 16;
                uint32_t kb = (uint32_t)(ks << 5) + bKsel;
                uint32_t addr = bS + (uint32_t)(row * 64)
                              + (kb ^ (uint32_t)(((row >> 1) & 3) << 4));
                ldsm_x4(b[p], addr);
            }
#pragma unroll
            for (int mi = 0; mi < 2; mi++)
#pragma unroll
                for (int nj = 0; nj < 8; nj++) {
                    int p = nj >> 1, e = (nj & 1) << 1;
                    mma16816(acc[mi][nj], a[mi], b[p][e], b[p][e + 1]);
                }
        }
        __syncthreads();
        if (c + 3 < 32) load_chunk(c + 3, st);
        if (++st == 3) st = 0;
    }

    // writeout fp32 accumulators
    float* C = g_Out + ((size_t)n << 19);
    int colBase = n0 + wn * 64 + ((lane & 3) << 1);
    int rowBase = m0 + wm * 32 + (lane >> 2);
#pragma unroll
    for (int mi = 0; mi < 2; mi++) {
        int r = rowBase + mi * 16;
#pragma unroll
        for (int nj = 0; nj < 8; nj++) {
            int col = colBase + nj * 8;
            *(float2*)&C[(size_t)r * GCOLS + col]       = make_float2(acc[mi][nj][0], acc[mi][nj][1]);
            *(float2*)&C[(size_t)(r + 8) * GCOLS + col] = make_float2(acc[mi][nj][2], acc[mi][nj][3]);
        }
    }
}

// ---------------------------------------------------------------------------
// Kernel 5: un-gather Out + residual x*omega + SiLU -> d_out (S,B,E) fp32
// 4 sequence positions per block.
// ---------------------------------------------------------------------------
__global__ __launch_bounds__(512) void epilogue_kernel(const float* __restrict__ x,
                                                       const float* __restrict__ omega,
                                                       float* __restrict__ out) {
    int blk = blockIdx.x;                 // 0..8191
    int b  = blk & 31;
    int s0 = (blk >> 5) << 2;             // 4 consecutive s
    __shared__ float sm[4][16 * 33 + 33];
    int tid = threadIdx.x;                // 512
    int nn = tid >> 4, r = tid & 15;
#pragma unroll
    for (int sv = 0; sv < 4; sv++)
        sm[sv][r * 33 + nn] = g_Out[((size_t)nn << 19) + (size_t)(s0 + sv) * GCOLS + b * 16 + r];
    __syncthreads();
    float om = omega[tid];
    int sidx = (tid >> 5) * 33 + (tid & 31);
#pragma unroll
    for (int sv = 0; sv < 4; sv++) {
        size_t off = (size_t)(s0 + sv) * (BSZ * EMBED) + (size_t)b * EMBED + tid;
        float z = sm[sv][sidx] + x[off] * om;
        out[off] = z / (1.0f + expf(-z));
    }
}

// ---------------------------------------------------------------------------
extern "C" void kernel_launch(void* const* d_in, const int* in_sizes, int n_in,
                              void* d_out, int out_size) {
    const float* x     = (const float*)d_in[0];
    const float* A1    = (const float*)d_in[1];
    const float* A2    = (const float*)d_in[2];
    const float* A3    = (const float*)d_in[3];
    const float* A4    = (const float*)d_in[4];
    const float* B1    = (const float*)d_in[5];
    const float* B2    = (const float*)d_in[6];
    const float* C1    = (const float*)d_in[7];
    const float* C2    = (const float*)d_in[8];
    const float* omega = (const float*)d_in[9];
    float* out = (float*)d_out;

    compute_k_kernel<<<8, 32>>>(A1, A2, A3, A4, B1, B2, C1, C2);
    build_M_kernel<<<dim3(32, GROUPS), 256>>>();
    transpose_kernel<<<SEQ * BSZ / 32, 256>>>(x);
    gemm_kernel<<<dim3(GCOLS / 128, 1024 / 128, GROUPS), 256>>>();
    epilogue_kernel<<<SEQ * BSZ / 4, 512>>>(x, omega, out);
}

// round 7
// speedup vs baseline: 4.9199x; 1.2698x over previous
#include <cuda_runtime.h>
#include <cuda_fp16.h>
#include <math.h>
#include <stdint.h>

// ---------------------------------------------------------------------------
// TwoDimensionalSSM: out = silu( conv4dir(x, k) + x*omega )
// M_n is 2-level Toeplitz: M[(i,j),(u,v)] = T_n(i-u, j-v), T = 63x63 table.
// GEMM Out_n = M_n @ X_n^T with A fragments generated from the smem table.
// ---------------------------------------------------------------------------

#define LSIDE  32
#define SEQ    1024
#define BSZ    32
#define EMBED  512
#define NSSM   32
#define KDIM   128
#define GROUPS 32
#define GCOLS  512
#define TROWS  63
#define TCOLSW 64          // padded row width
#define TSZ    (TROWS * TCOLSW)   // 4032 uint32 per group

// Static device scratch (allocation-free, graph-capturable)
__device__ float  g_kpart[2][KDIM][SEQ];                             // 1 MB
__device__ __align__(16) uint32_t g_Tp[(size_t)GROUPS * TSZ];        // 516 KB pair tables
__device__ __align__(16) __half g_X[(size_t)GROUPS * GCOLS * 1024];  // 32 MB  [n][c][s]
__device__ __align__(16) float  g_Out[(size_t)GROUPS * 1024 * GCOLS];// 64 MB  [n][sp][c]

__device__ __forceinline__ float sigmoidf_(float v) { return 1.0f / (1.0f + expf(-v)); }

__device__ __forceinline__ uint32_t smem_u32(const void* p) {
    return (uint32_t)__cvta_generic_to_shared(p);
}
__device__ __forceinline__ void cp_async16(uint32_t dst, const void* src) {
    asm volatile("cp.async.cg.shared.global [%0], [%1], 16;" :: "r"(dst), "l"(src) : "memory");
}
__device__ __forceinline__ void cp_commit() {
    asm volatile("cp.async.commit_group;" ::: "memory");
}
__device__ __forceinline__ uint32_t lds32(uint32_t addr) {
    uint32_t v;
    asm volatile("ld.shared.b32 %0, [%1];" : "=r"(v) : "r"(addr));
    return v;
}
__device__ __forceinline__ void ldsm_x4(uint32_t* r, uint32_t addr) {
    asm volatile("ldmatrix.sync.aligned.m8n8.x4.shared.b16 {%0,%1,%2,%3}, [%4];"
                 : "=r"(r[0]), "=r"(r[1]), "=r"(r[2]), "=r"(r[3]) : "r"(addr));
}
__device__ __forceinline__ void mma16816(float* c, const uint32_t* a, uint32_t b0, uint32_t b1) {
    asm volatile(
        "mma.sync.aligned.m16n8k16.row.col.f32.f16.f16.f32 "
        "{%0,%1,%2,%3}, {%4,%5,%6,%7}, {%8,%9}, {%0,%1,%2,%3};"
        : "+f"(c[0]), "+f"(c[1]), "+f"(c[2]), "+f"(c[3])
        : "r"(a[0]), "r"(a[1]), "r"(a[2]), "r"(a[3]), "r"(b0), "r"(b1));
}

// ---------------------------------------------------------------------------
// Kernel 1: 2-D SSM recurrence -> impulse response partials per (h, state n).
// ---------------------------------------------------------------------------
__global__ void compute_k_kernel(const float* __restrict__ A1p, const float* __restrict__ A2p,
                                 const float* __restrict__ A3p, const float* __restrict__ A4p,
                                 const float* __restrict__ B1p, const float* __restrict__ B2p,
                                 const float* __restrict__ C1p, const float* __restrict__ C2p) {
    int g = blockIdx.x * blockDim.x + threadIdx.x;
    if (g >= 2 * KDIM) return;
    int h = g >> 1, nn = g & 1;
    int idx = h * 2 + nn;
    float A1 = sigmoidf_(A1p[idx]);
    float A2 = sigmoidf_(A2p[idx]);
    float A3 = sigmoidf_(A3p[idx]);
    float A4 = sigmoidf_(A4p[idx]);
    float B1 = sigmoidf_(B1p[idx]);
    float B2 = sigmoidf_(B2p[idx]);
    const float scale = 0.70710678118654752f;
    float C1 = C1p[idx] * scale;
    float C2 = C2p[idx] * scale;

    float xh_up[LSIDE], xv_up[LSIDE];
#pragma unroll
    for (int j = 0; j < LSIDE; j++) { xh_up[j] = 0.0f; xv_up[j] = 0.0f; }

    float* kout = &g_kpart[nn][h][0];
    for (int i = 0; i < LSIDE; i++) {
        float xh_prev = 0.0f, xv_prev = 0.0f;
        for (int j = 0; j < LSIDE; j++) {
            float u = (i == 0 && j == 0) ? 1.0f : 0.0f;
            float xv_new  = A3 * xh_up[j] + A4 * xv_up[j] + B2 * u;
            float xv_left = (j == 0) ? 0.0f : xv_prev;
            float xh_new  = A1 * xh_prev + A2 * xv_left + B1 * u;
            kout[i * LSIDE + j] = C1 * xh_new + C2 * xv_new;
            xh_up[j] = xh_new; xv_up[j] = xv_new;
            xh_prev  = xh_new; xv_prev  = xv_new;
        }
    }
}

// ---------------------------------------------------------------------------
// Kernel 2: build Toeplitz pair tables.
//  T(da,db) = sum over quadrant kernels (>=/<= conditions handle the da==0 /
//  db==0 overlaps exactly as the 4-direction sum does).
//  Spair[da+31][p] = half2( T[da][32-p], T[da][31-p] )   (p = 32 - db)
// ---------------------------------------------------------------------------
__global__ __launch_bounds__(256) void build_T_kernel() {
    int n = blockIdx.x;
    __shared__ float sk[4][1024];
    int tid = threadIdx.x;
#pragma unroll
    for (int it = 0; it < 16; it++) {
        int idx = tid + it * 256;
        int d  = idx >> 10;
        int ab = idx & 1023;
        int a = ab >> 5, b = ab & 31;
        float v = g_kpart[0][d * NSSM + n][ab] + g_kpart[1][d * NSSM + n][ab];
        float f = 1.0f;
        if (!(a == 0 && b == 0)) {
            if (a == 0) f *= 2.0f;
            if (b == 0) f *= 2.0f;
        }
        sk[d][ab] = v * f;
    }
    __syncthreads();

    auto Tval = [&](int da, int db) -> float {
        if (db > 31 || db < -31) return 0.0f;
        int a = da < 0 ? -da : da;
        int b = db < 0 ? -db : db;
        int idx = a * 32 + b;
        float r = 0.0f;
        if (da >= 0 && db >= 0) r += sk[0][idx];
        if (da <= 0 && db >= 0) r += sk[1][idx];
        if (da >= 0 && db <= 0) r += sk[2][idx];
        if (da <= 0 && db <= 0) r += sk[3][idx];
        return r;
    };

#pragma unroll
    for (int t = 0; t < 16; t++) {
        int e = tid + t * 256;
        if (e < TSZ) {
            int da = (e >> 6) - 31;
            int p  = e & 63;
            __half2 h = __floats2half2_rn(Tval(da, 32 - p), Tval(da, 31 - p));
            g_Tp[(size_t)n * TSZ + e] = *(uint32_t*)&h;
        }
    }
}

// ---------------------------------------------------------------------------
// Kernel 3: gather/transpose x (S,B,E) fp32 -> g_X[n][c][s] fp16  (c=b*16+e/32)
// ---------------------------------------------------------------------------
__global__ __launch_bounds__(256) void transpose_kernel(const float* __restrict__ x) {
    __shared__ __half sm[32][520];
    int b  = blockIdx.x & 31;
    int s0 = (blockIdx.x >> 5) << 5;
    int t = threadIdx.x;
#pragma unroll
    for (int i = 0; i < 64; ++i) {
        int idx = t + (i << 8);
        int si = idx >> 9, e = idx & 511;
        sm[si][e] = __float2half_rn(x[(size_t)(s0 + si) * (BSZ * EMBED) + (size_t)b * EMBED + e]);
    }
    __syncthreads();
#pragma unroll
    for (int i = 0; i < 8; ++i) {
        int c2 = t + (i << 8);
        int pair = c2 >> 2, sj = (c2 & 3) << 3;
        int nn = pair & 31, r = pair >> 5;
        int e = (r << 5) + nn;
        __half tmp[8];
#pragma unroll
        for (int q = 0; q < 8; ++q) tmp[q] = sm[sj + q][e];
        *(uint4*)&g_X[((size_t)nn * GCOLS + b * 16 + r) * 1024 + s0 + sj] = *(uint4*)tmp;
    }
}

// ---------------------------------------------------------------------------
// Kernel 4: Toeplitz HMMA GEMM. CTA tile 128(M)x128(N), BK=64, 16 chunks,
// double-buffered B via cp.async (2 x 16KB) + Spair table (16128B) = ~48KB.
// A fragments come from the table: A[m=(i,j)][k=(u,v)] = T[i-u][j-v]
//   = Spair[(i-u)+31][32-j+v]  (lo = v, hi = v+1)  -> one aligned LDS.32.
// 8 warps (4M x 2N), warp tile 32x64.
// ---------------------------------------------------------------------------
__global__ __launch_bounds__(256) void gemm_kernel() {
    __shared__ __align__(1024) __half bbuf[2 * 128 * 64];   // 32 KB B stages
    __shared__ __align__(16) uint32_t spair[TSZ];           // 16128 B table

    const int n  = blockIdx.z;
    const int m0 = blockIdx.y << 7;
    const int n0 = blockIdx.x << 7;
    const __half* Bg = g_X + ((size_t)n << 19);

    const int tid = threadIdx.x;
    const int wid = tid >> 5;
    const int lane = tid & 31;
    const int wm = wid & 3;          // 4 warps along M (32 rows each)
    const int wn = wid >> 2;         // 2 warps along N (64 cols each)

    const uint32_t sB = smem_u32(bbuf);
    const uint32_t sT = smem_u32(spair);
    const uint32_t B_STG = 16384;

    // table load (cp.async group 0)
    {
        const uint32_t* src = g_Tp + (size_t)n * TSZ;
#pragma unroll
        for (int i = 0; i < 4; ++i) {
            int id = tid + (i << 8);
            if (id < TSZ / 4) cp_async16(sT + id * 16, src + id * 4);
        }
        cp_commit();
    }

    auto load_chunk = [&](int c, int st) {
        int k0 = c << 6;
#pragma unroll
        for (int i = 0; i < 4; ++i) {            // B: 128 rows x 8 x 16B
            int id  = tid + (i << 8);            // 0..1023
            int row = id >> 3, k8 = id & 7;
            uint32_t sw = (uint32_t)(row * 128 + ((k8 << 4) ^ ((row & 7) << 4)));
            cp_async16(sB + (uint32_t)st * B_STG + sw,
                       Bg + (size_t)(n0 + row) * 1024 + k0 + (k8 << 3));
        }
        cp_commit();
    };

    load_chunk(0, 0);
    load_chunk(1, 1);

    float acc[2][8][4];
#pragma unroll
    for (int mi = 0; mi < 2; mi++)
#pragma unroll
        for (int nj = 0; nj < 8; nj++)
#pragma unroll
            for (int q = 0; q < 4; q++) acc[mi][nj][q] = 0.0f;

    // A base addresses: per mi, two rows (r, r+8) of the 16x16 fragment.
    // base = &Spair[(i+31)*64 + (32 - j) + (lane&3)*2]  (bytes)
    uint32_t pA[2][2];
#pragma unroll
    for (int mi = 0; mi < 2; mi++) {
#pragma unroll
        for (int rh = 0; rh < 2; rh++) {
            int sp = m0 + wm * 32 + mi * 16 + (lane >> 2) + rh * 8;
            int i = sp >> 5, j = sp & 31;
            pA[mi][rh] = sT + (uint32_t)(((i + 31) * 64 + (32 - j) + (lane & 3) * 2) * 4);
        }
    }

    // B ldmatrix lane geometry (as validated in prior rounds)
    const int bRow0 = wn * 64 + (lane & 7) + ((lane & 16) >> 1);   // + p*16
    const uint32_t bKsel = (uint32_t)((lane & 8) << 1);            // 0 or 16 bytes

    for (int c = 0; c < 16; ++c) {
        if (c < 14)       asm volatile("cp.async.wait_group 1;" ::: "memory");
        else              asm volatile("cp.async.wait_group 0;" ::: "memory");
        __syncthreads();

        uint32_t bS = sB + (uint32_t)(c & 1) * B_STG;

#pragma unroll
        for (int ks = 0; ks < 4; ++ks) {
            int u = 2 * c + (ks >> 1);
            int aoff = ((ks & 1) << 6) - (u << 8);   // ((ks&1)*16)*4 - u*64*4 bytes

            uint32_t a[2][4];
#pragma unroll
            for (int mi = 0; mi < 2; mi++) {
                a[mi][0] = lds32(pA[mi][0] + aoff);        // (r,   k lo8)
                a[mi][1] = lds32(pA[mi][1] + aoff);        // (r+8, k lo8)
                a[mi][2] = lds32(pA[mi][0] + aoff + 32);   // (r,   k hi8)
                a[mi][3] = lds32(pA[mi][1] + aoff + 32);   // (r+8, k hi8)
            }
            uint32_t b[4][4];
#pragma unroll
            for (int p = 0; p < 4; p++) {
                int row = bRow0 + p * 16;
                uint32_t kb = (uint32_t)(ks << 5) + bKsel;
                uint32_t addr = bS + (uint32_t)(row * 128)
                              + (kb ^ (uint32_t)((row & 7) << 4));
                ldsm_x4(b[p], addr);
            }
#pragma unroll
            for (int mi = 0; mi < 2; mi++)
#pragma unroll
                for (int nj = 0; nj < 8; nj++) {
                    int p = nj >> 1, e = (nj & 1) << 1;
                    mma16816(acc[mi][nj], a[mi], b[p][e], b[p][e + 1]);
                }
        }
        __syncthreads();
        if (c + 2 < 16) load_chunk(c + 2, c & 1);
    }

    // writeout fp32 accumulators
    float* C = g_Out + ((size_t)n << 19);
    int colBase = n0 + wn * 64 + ((lane & 3) << 1);
    int rowBase = m0 + wm * 32 + (lane >> 2);
#pragma unroll
    for (int mi = 0; mi < 2; mi++) {
        int r = rowBase + mi * 16;
#pragma unroll
        for (int nj = 0; nj < 8; nj++) {
            int col = colBase + nj * 8;
            *(float2*)&C[(size_t)r * GCOLS + col]       = make_float2(acc[mi][nj][0], acc[mi][nj][1]);
            *(float2*)&C[(size_t)(r + 8) * GCOLS + col] = make_float2(acc[mi][nj][2], acc[mi][nj][3]);
        }
    }
}

// ---------------------------------------------------------------------------
// Kernel 5: un-gather Out + residual x*omega + SiLU -> d_out (S,B,E) fp32
// ---------------------------------------------------------------------------
__global__ __launch_bounds__(512) void epilogue_kernel(const float* __restrict__ x,
                                                       const float* __restrict__ omega,
                                                       float* __restrict__ out) {
    int blk = blockIdx.x;                 // 0..8191
    int b  = blk & 31;
    int s0 = (blk >> 5) << 2;             // 4 consecutive s
    __shared__ float sm[4][16 * 33 + 33];
    int tid = threadIdx.x;                // 512
    int nn = tid >> 4, r = tid & 15;
#pragma unroll
    for (int sv = 0; sv < 4; sv++)
        sm[sv][r * 33 + nn] = g_Out[((size_t)nn << 19) + (size_t)(s0 + sv) * GCOLS + b * 16 + r];
    __syncthreads();
    float om = omega[tid];
    int sidx = (tid >> 5) * 33 + (tid & 31);
#pragma unroll
    for (int sv = 0; sv < 4; sv++) {
        size_t off = (size_t)(s0 + sv) * (BSZ * EMBED) + (size_t)b * EMBED + tid;
        float z = sm[sv][sidx] + x[off] * om;
        out[off] = z / (1.0f + expf(-z));
    }
}

// ---------------------------------------------------------------------------
extern "C" void kernel_launch(void* const* d_in, const int* in_sizes, int n_in,
                              void* d_out, int out_size) {
    const float* x     = (const float*)d_in[0];
    const float* A1    = (const float*)d_in[1];
    const float* A2    = (const float*)d_in[2];
    const float* A3    = (const float*)d_in[3];
    const float* A4    = (const float*)d_in[4];
    const float* B1    = (const float*)d_in[5];
    const float* B2    = (const float*)d_in[6];
    const float* C1    = (const float*)d_in[7];
    const float* C2    = (const float*)d_in[8];
    const float* omega = (const float*)d_in[9];
    float* out = (float*)d_out;

    compute_k_kernel<<<8, 32>>>(A1, A2, A3, A4, B1, B2, C1, C2);
    build_T_kernel<<<GROUPS, 256>>>();
    transpose_kernel<<<SEQ * BSZ / 32, 256>>>(x);
    gemm_kernel<<<dim3(GCOLS / 128, 1024 / 128, GROUPS), 256>>>();
    epilogue_kernel<<<SEQ * BSZ / 4, 512>>>(x, omega, out);
}